// round 3
// baseline (speedup 1.0000x reference)
#include <cuda_runtime.h>

#define NN   3072
#define EE   3072
#define ELG  6144
#define FF   64
#define HH   4
#define RPH  768   // input rows per head after .view scramble

// -------- scratch (__device__ globals; no allocations allowed) --------
__device__ float g_NV[NN * 256];
__device__ float g_EV[EE * 256];
__device__ float g_srkp[2 * 48 * 4 * 64];   // partial srk sums [g][chunk][h][f]
__device__ float g_WT[2 * 256 * 64];        // transposed Wq (node, edge)
__device__ float g_att[2 * 4 * 3072];       // g=0: node att, g=1: edge att
__device__ unsigned char g_winN[EE];
__device__ unsigned char g_winL[ELG];

// ======================= kernel A: all input-only work =======================
// roles by blockIdx.x:
//   [0,96)        srk partials (fused K projection, never materialized)
//   [96,480)      V gemms: NV (192 blocks), EV (192 blocks)
//   [480,1056)    dedup winners: node (192), line-graph (384)
//   [1056,1440)   zero output
//   [1440,1448)   transpose Wq (node 4 tiles, edge 4 tiles)
__global__ void __launch_bounds__(256) kA(
    const float* nin, const float* ein,
    const float* nkW, const float* nkb, const float* ekW, const float* ekb,
    const float* nvW, const float* nvb, const float* evW, const float* evb,
    const float* nqW, const float* eqW,
    const int* src, const int* dst, const int* lgs, const int* lgd,
    float* out)
{
    __shared__ float sm[64 * 65 + 64 * 64 + 64];   // unioned per role
    int b = blockIdx.x, tid = threadIdx.x;

    if (b < 96) {
        // ---- srk role: chunk of 64 nodes (16 KM rows per head) ----
        int g = b / 48, chunk = b % 48;
        const float* in = g ? ein : nin;
        const float* W  = g ? ekW : nkW;
        const float* bk = g ? ekb : nkb;
        float* s_in4 = sm;           // 4 * 16 * 65 = 4160
        float* s_km  = sm + 4224;    // 4 * 64

        #pragma unroll
        for (int h2 = 0; h2 < 4; h2++) {
            #pragma unroll
            for (int i = 0; i < 4; i++) {
                int idx = i * 256 + tid;
                int rr = idx >> 6, kk = idx & 63;
                s_in4[h2 * 1040 + rr * 65 + kk] =
                    in[(h2 * RPH + chunk * 16 + rr) * 64 + kk];
            }
        }
        __syncthreads();
        // phase 1: KM entries: k[h, n] = KM[h*768 + n/4, n%4]
        int h = tid >> 6, idx = tid & 63;
        int rl = idx >> 2, c = idx & 3;
        float acc = bk[c];
        #pragma unroll
        for (int k = 0; k < 64; k++)
            acc += s_in4[h * 1040 + rl * 65 + k] * W[k * 4 + c];
        s_km[h * 64 + rl * 4 + c] = acc;   // index == h*64 + local n
        __syncthreads();
        // phase 2: srk partial: srk[h,f] += in[n,f] * k[h,n] over 64 n
        int f = tid & 63;
        float sacc = 0.f;
        int n0 = chunk * 64;
        #pragma unroll 8
        for (int nl = 0; nl < 64; nl++)
            sacc += in[(n0 + nl) * 64 + f] * s_km[h * 64 + nl];
        g_srkp[((g * 48 + chunk) * 4 + h) * 64 + f] = sacc;

    } else if (b < 480) {
        // ---- V gemm role: [3072x64] @ [64x256] + bias ----
        int i2 = b - 96;
        int mat = i2 / 192;
        int rem = i2 % 192;
        int r0 = (rem >> 2) * 64, c0 = (rem & 3) * 64;
        const float* in = mat ? ein : nin;
        const float* W  = mat ? evW : nvW;
        const float* bb = mat ? evb : nvb;
        float* outv     = mat ? g_EV : g_NV;
        float* As = sm;                  // 64*65
        float* Ws = sm + 64 * 65;        // 64*64
        float* Bs = sm + 64 * 65 + 64 * 64;

        #pragma unroll
        for (int i = 0; i < 16; i++) {
            int idx = i * 256 + tid;
            int r = idx >> 6, k = idx & 63;
            As[k * 65 + r] = in[r0 * 64 + idx];
        }
        #pragma unroll
        for (int i = 0; i < 16; i++) {
            int idx = i * 256 + tid;
            int k = idx >> 6, cc = idx & 63;
            Ws[k * 64 + cc] = W[k * 256 + c0 + cc];
        }
        if (tid < 64) Bs[tid] = bb[c0 + tid];
        __syncthreads();

        int tx = tid & 15, ty = tid >> 4;
        int rl = ty * 4, cl = tx * 4;
        float acc[4][4];
        #pragma unroll
        for (int i = 0; i < 4; i++)
            #pragma unroll
            for (int j = 0; j < 4; j++) acc[i][j] = Bs[cl + j];

        #pragma unroll 16
        for (int k = 0; k < 64; k++) {
            float a0 = As[k * 65 + rl + 0];
            float a1 = As[k * 65 + rl + 1];
            float a2 = As[k * 65 + rl + 2];
            float a3 = As[k * 65 + rl + 3];
            float4 w = *(const float4*)&Ws[k * 64 + cl];
            acc[0][0] += a0 * w.x; acc[0][1] += a0 * w.y; acc[0][2] += a0 * w.z; acc[0][3] += a0 * w.w;
            acc[1][0] += a1 * w.x; acc[1][1] += a1 * w.y; acc[1][2] += a1 * w.z; acc[1][3] += a1 * w.w;
            acc[2][0] += a2 * w.x; acc[2][1] += a2 * w.y; acc[2][2] += a2 * w.z; acc[2][3] += a2 * w.w;
            acc[3][0] += a3 * w.x; acc[3][1] += a3 * w.y; acc[3][2] += a3 * w.z; acc[3][3] += a3 * w.w;
        }
        #pragma unroll
        for (int i = 0; i < 4; i++) {
            float4 v = make_float4(acc[i][0], acc[i][1], acc[i][2], acc[i][3]);
            *(float4*)&outv[(r0 + rl + i) * 256 + c0 + cl] = v;
        }

    } else if (b < 1056) {
        // ---- dedup winner role: last-write-wins => max index per key ----
        int i2 = b - 480;
        const int *ka, *kb2; int M; unsigned char* win; int e0;
        if (i2 < 192) { ka = src; kb2 = dst; M = EE;  win = g_winN; e0 = i2 * 16; }
        else { i2 -= 192; ka = lgs; kb2 = lgd; M = ELG; win = g_winL; e0 = i2 * 16; }
        int e = e0 + (tid >> 4);
        int s = tid & 15;
        int ke = ka[e] * 8192 + kb2[e];
        bool lose = false;
        #pragma unroll 4
        for (int j = e + 1 + s; j < M; j += 16)
            lose |= (ka[j] * 8192 + kb2[j] == ke);
        unsigned bal = __ballot_sync(0xffffffffu, lose);
        unsigned gm = 0xffffu << (tid & 16);
        if (s == 0) win[e] = ((bal & gm) == 0) ? 1 : 0;

    } else if (b < 1440) {
        // ---- zero output ----
        int idx = (b - 1056) * 256 + tid;
        ((float4*)out)[idx] = make_float4(0.f, 0.f, 0.f, 0.f);

    } else {
        // ---- transpose Wq: [64k][256c] -> WT[256c][64k] ----
        int t = b - 1440;
        int mat = t >> 2, tile = t & 3;
        const float* W = mat ? eqW : nqW;
        float* s = sm;   // 64*65
        #pragma unroll
        for (int i = 0; i < 16; i++) {
            int idx = i * 256 + tid;
            int k = idx >> 6, c = idx & 63;
            s[k * 65 + c] = W[k * 256 + tile * 64 + c];
        }
        __syncthreads();
        #pragma unroll
        for (int i = 0; i < 16; i++) {
            int idx = i * 256 + tid;
            int c = idx >> 6, k = idx & 63;
            g_WT[mat * 16384 + (tile * 64 + c) * 64 + k] = s[k * 65 + c];
        }
    }
}

// ===== kernel BC: fused srk-reduce + c/d + logits + softmax, per (g,h) =====
__global__ void __launch_bounds__(1024) kBC(
    const float* nin, const float* ein, const float* nqb, const float* eqb)
{
    __shared__ float s_part[1024];
    __shared__ float s_srk[64];
    __shared__ float s_c[4 * 68];     // padded: bank-conflict-free per-j float4 reads
    __shared__ float s_d[4];
    __shared__ float s_x[3072];
    __shared__ float s_red[32];
    __shared__ float s_v;

    int g = blockIdx.x >> 2, h = blockIdx.x & 3;
    int tid = threadIdx.x;
    const float* in = g ? ein : nin;

    // ---- phase 1: reduce srk partials (48 chunks) ----
    {
        int f = tid & 63, p = tid >> 6;    // 16 groups x 3 chunks
        float a = 0.f;
        #pragma unroll
        for (int q = 0; q < 3; q++)
            a += g_srkp[((g * 48 + p * 3 + q) * 4 + h) * 64 + f];
        s_part[tid] = a;
    }
    __syncthreads();
    if (tid < 64) {
        float a = 0.f;
        #pragma unroll
        for (int p = 0; p < 16; p++) a += s_part[p * 64 + tid];
        s_srk[tid] = a;
    }
    __syncthreads();

    // ---- phase 2: c[j][k] = sum_f Wq[k,64j+f]*srk[f];  d[j] = bq[j]::srk ----
    if (tid < 256) {
        int j = tid & 3, k = tid >> 2;
        const float* wt = g_WT + g * 16384 + j * 4096;   // WT[(j*64+f)*64 + k]
        float a = 0.f;
        #pragma unroll
        for (int f = 0; f < 64; f++)
            a += wt[f * 64 + k] * s_srk[f];
        s_c[j * 68 + k] = a;
    } else if (tid < 260) {
        int j = tid - 256;
        const float* bq = g ? eqb : nqb;
        float dd = 0.f;
        #pragma unroll
        for (int f = 0; f < 64; f++) dd += bq[j * 64 + f] * s_srk[f];
        s_d[j] = dd;
    }
    __syncthreads();

    // ---- phase 3: logits for all 3072 positions ----
    float lmax = -1e30f;
    #pragma unroll
    for (int i = 0; i < 3; i++) {
        int n = tid + i * 1024;
        int m = n >> 2, j = n & 3;
        const float4* row = (const float4*)(in + ((size_t)(h * RPH + m)) * 64);
        const float4* cj  = (const float4*)(s_c + j * 68);
        float a0 = 0.f, a1 = 0.f, a2 = 0.f, a3 = 0.f;
        #pragma unroll
        for (int k = 0; k < 16; k += 4) {
            float4 r0 = row[k + 0], c0 = cj[k + 0];
            float4 r1 = row[k + 1], c1 = cj[k + 1];
            float4 r2 = row[k + 2], c2 = cj[k + 2];
            float4 r3 = row[k + 3], c3 = cj[k + 3];
            a0 += r0.x * c0.x + r0.y * c0.y + r0.z * c0.z + r0.w * c0.w;
            a1 += r1.x * c1.x + r1.y * c1.y + r1.z * c1.z + r1.w * c1.w;
            a2 += r2.x * c2.x + r2.y * c2.y + r2.z * c2.z + r2.w * c2.w;
            a3 += r3.x * c3.x + r3.y * c3.y + r3.z * c3.z + r3.w * c3.w;
        }
        float x = (s_d[j] + ((a0 + a1) + (a2 + a3))) * 0.125f;
        s_x[n] = x;
        lmax = fmaxf(lmax, x);
    }

    // ---- phase 4: softmax over 3072 ----
    #pragma unroll
    for (int o = 16; o > 0; o >>= 1)
        lmax = fmaxf(lmax, __shfl_xor_sync(0xffffffffu, lmax, o));
    if ((tid & 31) == 0) s_red[tid >> 5] = lmax;
    __syncthreads();
    if (tid == 0) {
        float m2 = s_red[0];
        #pragma unroll
        for (int i = 1; i < 32; i++) m2 = fmaxf(m2, s_red[i]);
        s_v = m2;
    }
    __syncthreads();
    float mx = s_v;
    float e0 = __expf(s_x[tid]        - mx);
    float e1 = __expf(s_x[tid + 1024] - mx);
    float e2 = __expf(s_x[tid + 2048] - mx);
    float lsum = e0 + e1 + e2;
    #pragma unroll
    for (int o = 16; o > 0; o >>= 1)
        lsum += __shfl_xor_sync(0xffffffffu, lsum, o);
    __syncthreads();
    if ((tid & 31) == 0) s_red[tid >> 5] = lsum;
    __syncthreads();
    if (tid == 0) {
        float s = 0.f;
        #pragma unroll
        for (int i = 0; i < 32; i++) s += s_red[i];
        s_v = 1.f / s;
    }
    __syncthreads();
    float inv = s_v;
    float* att = g_att + (g * 4 + h) * 3072;
    att[tid]        = e0 * inv;
    att[tid + 1024] = e1 * inv;
    att[tid + 2048] = e2 * inv;
}

// ======================= kernel D: message-passing scatter =======================
__global__ void __launch_bounds__(256) kD(
    const int* src, const int* dst, const int* lgs, const int* lgd, float* out)
{
    int tid = threadIdx.x;
    int u = tid >> 6, f = tid & 63;
    int bx = blockIdx.x;
    if (bx < 768) {                                    // node messages (use edge att, g=1)
        int e = bx * 4 + u;
        if (!g_winN[e]) return;
        int s = src[e], d = dst[e];
        float acc = 0.f;
        #pragma unroll
        for (int h = 0; h < 4; h++)
            acc += __ldg(&g_att[(4 + h) * 3072 + e]) * g_NV[((size_t)(h * 3072 + d)) * 64 + f];
        atomicAdd(&out[s * 64 + f], 0.25f * acc);      // mean over heads
    } else {                                           // line-graph messages (use node att, g=0)
        int l = (bx - 768) * 4 + u;
        if (!g_winL[l]) return;
        int e1 = lgs[l], e2 = lgd[l];
        int c = dst[e1];
        float acc = 0.f;
        #pragma unroll
        for (int h = 0; h < 4; h++)
            acc += __ldg(&g_att[h * 3072 + c]) * g_EV[((size_t)(h * 3072 + e2)) * 64 + f];
        atomicAdd(&out[NN * 64 + e1 * 64 + f], 0.25f * acc);
    }
}

extern "C" void kernel_launch(void* const* d_in, const int* in_sizes, int n_in,
                              void* d_out, int out_size)
{
    const float* nin = (const float*)d_in[0];
    const float* ein = (const float*)d_in[1];
    const int* src = (const int*)d_in[2];
    const int* dst = (const int*)d_in[3];
    const int* lgs = (const int*)d_in[4];
    const int* lgd = (const int*)d_in[5];
    const float* nqW = (const float*)d_in[6];  const float* nqb = (const float*)d_in[7];
    const float* nkW = (const float*)d_in[8];  const float* nkb = (const float*)d_in[9];
    const float* nvW = (const float*)d_in[10]; const float* nvb = (const float*)d_in[11];
    const float* eqW = (const float*)d_in[12]; const float* eqb = (const float*)d_in[13];
    const float* ekW = (const float*)d_in[14]; const float* ekb = (const float*)d_in[15];
    const float* evW = (const float*)d_in[16]; const float* evb = (const float*)d_in[17];
    float* out = (float*)d_out;

    kA<<<1448, 256>>>(nin, ein, nkW, nkb, ekW, ekb, nvW, nvb, evW, evb,
                      nqW, eqW, src, dst, lgs, lgd, out);
    kBC<<<8, 1024>>>(nin, ein, nqb, eqb);
    kD<<<2304, 256>>>(src, dst, lgs, lgd, out);
}

// round 4
// speedup vs baseline: 1.4810x; 1.4810x over previous
#include <cuda_runtime.h>

#define NN   3072
#define EE   3072
#define ELG  6144
#define FF   64
#define HH   4
#define RPH  768        // input rows per head after .view scramble
#define TABH 9437184    // 3072*3072, lg keys offset by this

// -------- scratch (__device__ globals; no allocations allowed) --------
__device__ float g_NV[NN * 256];
__device__ float g_EV[EE * 256];
__device__ float g_srkp[2 * 48 * 4 * 64];   // partial srk sums [g][chunk][h][f]
__device__ float g_WT[2 * 256 * 64];        // transposed Wq (node, edge)
__device__ float g_att[2 * 4 * 3072];       // g=0: node att, g=1: edge att
__device__ unsigned char g_winN[EE];
__device__ unsigned char g_winL[ELG];
__device__ int g_tab[2 * TABH];             // dedup tournament table (zero invariant)

// ======================= kernel A: all input-only work =======================
// roles by blockIdx.x:
//   [0,96)      srk partials (fused K projection, never materialized)
//   [96,480)    V gemms: NV (192 blocks), EV (192 blocks)
//   [480,516)   dedup atomicMax tournament (9216 edges)
//   [516,900)   zero output
//   [900,908)   transpose Wq (node 4 tiles, edge 4 tiles)
__global__ void __launch_bounds__(256) kA(
    const float* nin, const float* ein,
    const float* nkW, const float* nkb, const float* ekW, const float* ekb,
    const float* nvW, const float* nvb, const float* evW, const float* evb,
    const float* nqW, const float* eqW,
    const int* src, const int* dst, const int* lgs, const int* lgd,
    float* out)
{
    __shared__ float sm[64 * 65 + 64 * 64 + 64];   // unioned per role
    int b = blockIdx.x, tid = threadIdx.x;

    if (b < 96) {
        // ---- srk role: chunk of 64 nodes (16 KM rows per head) ----
        int g = b / 48, chunk = b % 48;
        const float* in = g ? ein : nin;
        const float* W  = g ? ekW : nkW;
        const float* bk = g ? ekb : nkb;
        float* s_in4 = sm;           // 4 * 16 * 65 = 4160
        float* s_km  = sm + 4224;    // 4 * 64

        #pragma unroll
        for (int h2 = 0; h2 < 4; h2++) {
            #pragma unroll
            for (int i = 0; i < 4; i++) {
                int idx = i * 256 + tid;
                int rr = idx >> 6, kk = idx & 63;
                s_in4[h2 * 1040 + rr * 65 + kk] =
                    in[(h2 * RPH + chunk * 16 + rr) * 64 + kk];
            }
        }
        __syncthreads();
        // phase 1: k[h, n] = KM[h*768 + n/4, n%4]
        int h = tid >> 6, idx = tid & 63;
        int rl = idx >> 2, c = idx & 3;
        float acc = bk[c];
        #pragma unroll
        for (int k = 0; k < 64; k++)
            acc += s_in4[h * 1040 + rl * 65 + k] * W[k * 4 + c];
        s_km[h * 64 + rl * 4 + c] = acc;   // index == h*64 + local n
        __syncthreads();
        // phase 2: srk partial: srk[h,f] += in[n,f] * k[h,n] over 64 n
        int f = tid & 63;
        float sacc = 0.f;
        int n0 = chunk * 64;
        #pragma unroll 8
        for (int nl = 0; nl < 64; nl++)
            sacc += in[(n0 + nl) * 64 + f] * s_km[h * 64 + nl];
        g_srkp[((g * 48 + chunk) * 4 + h) * 64 + f] = sacc;

    } else if (b < 480) {
        // ---- V gemm role: [3072x64] @ [64x256] + bias ----
        int i2 = b - 96;
        int mat = i2 / 192;
        int rem = i2 % 192;
        int r0 = (rem >> 2) * 64, c0 = (rem & 3) * 64;
        const float* in = mat ? ein : nin;
        const float* W  = mat ? evW : nvW;
        const float* bb = mat ? evb : nvb;
        float* outv     = mat ? g_EV : g_NV;
        float* As = sm;                  // 64*65
        float* Ws = sm + 64 * 65;        // 64*64
        float* Bs = sm + 64 * 65 + 64 * 64;

        #pragma unroll
        for (int i = 0; i < 16; i++) {
            int idx = i * 256 + tid;
            int r = idx >> 6, k = idx & 63;
            As[k * 65 + r] = in[r0 * 64 + idx];
        }
        #pragma unroll
        for (int i = 0; i < 16; i++) {
            int idx = i * 256 + tid;
            int k = idx >> 6, cc = idx & 63;
            Ws[k * 64 + cc] = W[k * 256 + c0 + cc];
        }
        if (tid < 64) Bs[tid] = bb[c0 + tid];
        __syncthreads();

        int tx = tid & 15, ty = tid >> 4;
        int rl = ty * 4, cl = tx * 4;
        float acc[4][4];
        #pragma unroll
        for (int i = 0; i < 4; i++)
            #pragma unroll
            for (int j = 0; j < 4; j++) acc[i][j] = Bs[cl + j];

        #pragma unroll 16
        for (int k = 0; k < 64; k++) {
            float a0 = As[k * 65 + rl + 0];
            float a1 = As[k * 65 + rl + 1];
            float a2 = As[k * 65 + rl + 2];
            float a3 = As[k * 65 + rl + 3];
            float4 w = *(const float4*)&Ws[k * 64 + cl];
            acc[0][0] += a0 * w.x; acc[0][1] += a0 * w.y; acc[0][2] += a0 * w.z; acc[0][3] += a0 * w.w;
            acc[1][0] += a1 * w.x; acc[1][1] += a1 * w.y; acc[1][2] += a1 * w.z; acc[1][3] += a1 * w.w;
            acc[2][0] += a2 * w.x; acc[2][1] += a2 * w.y; acc[2][2] += a2 * w.z; acc[2][3] += a2 * w.w;
            acc[3][0] += a3 * w.x; acc[3][1] += a3 * w.y; acc[3][2] += a3 * w.z; acc[3][3] += a3 * w.w;
        }
        #pragma unroll
        for (int i = 0; i < 4; i++) {
            float4 v = make_float4(acc[i][0], acc[i][1], acc[i][2], acc[i][3]);
            *(float4*)&outv[(r0 + rl + i) * 256 + c0 + cl] = v;
        }

    } else if (b < 516) {
        // ---- dedup tournament: atomicMax(tab[key], e+1) ----
        int e = (b - 480) * 256 + tid;
        if (e < EE) {
            atomicMax(&g_tab[src[e] * 3072 + dst[e]], e + 1);
        } else {
            int l = e - EE;
            atomicMax(&g_tab[TABH + lgs[l] * 3072 + lgd[l]], l + 1);
        }

    } else if (b < 900) {
        // ---- zero output ----
        int idx = (b - 516) * 256 + tid;
        ((float4*)out)[idx] = make_float4(0.f, 0.f, 0.f, 0.f);

    } else {
        // ---- transpose Wq: [64k][256c] -> WT[256c][64k] ----
        int t = b - 900;
        int mat = t >> 2, tile = t & 3;
        const float* W = mat ? eqW : nqW;
        float* s = sm;   // 64*65
        #pragma unroll
        for (int i = 0; i < 16; i++) {
            int idx = i * 256 + tid;
            int k = idx >> 6, c = idx & 63;
            s[k * 65 + c] = W[k * 256 + tile * 64 + c];
        }
        __syncthreads();
        #pragma unroll
        for (int i = 0; i < 16; i++) {
            int idx = i * 256 + tid;
            int c = idx >> 6, k = idx & 63;
            g_WT[mat * 16384 + (tile * 64 + c) * 64 + k] = s[k * 65 + c];
        }
    }
}

// ===== kernel BC: fused srk-reduce + c/d + logits + softmax (blocks 0-7) =====
// ===== blocks 8-16: read dedup winners from tournament table            =====
__global__ void __launch_bounds__(1024) kBC(
    const float* nin, const float* ein, const float* nqb, const float* eqb,
    const int* src, const int* dst, const int* lgs, const int* lgd)
{
    int tid = threadIdx.x;
    if (blockIdx.x >= 8) {
        int idx = (blockIdx.x - 8) * 1024 + tid;
        if (idx < EE) {
            g_winN[idx] = (g_tab[src[idx] * 3072 + dst[idx]] == idx + 1);
        } else if (idx < EE + ELG) {
            int l = idx - EE;
            g_winL[l] = (g_tab[TABH + lgs[l] * 3072 + lgd[l]] == l + 1);
        }
        return;
    }

    __shared__ float s_part[1024];
    __shared__ float s_srk[64];
    __shared__ float s_c[4 * 68];     // padded
    __shared__ float s_d[4];
    __shared__ float s_x[3072];
    __shared__ float s_red[32];
    __shared__ float s_v;

    int g = blockIdx.x >> 2, h = blockIdx.x & 3;
    const float* in = g ? ein : nin;

    // ---- phase 1: reduce srk partials (48 chunks) ----
    {
        int f = tid & 63, p = tid >> 6;    // 16 groups x 3 chunks
        float a = 0.f;
        #pragma unroll
        for (int q = 0; q < 3; q++)
            a += g_srkp[((g * 48 + p * 3 + q) * 4 + h) * 64 + f];
        s_part[tid] = a;
    }
    __syncthreads();
    if (tid < 64) {
        float a = 0.f;
        #pragma unroll
        for (int p = 0; p < 16; p++) a += s_part[p * 64 + tid];
        s_srk[tid] = a;
    }
    __syncthreads();

    // ---- phase 2: c[j][k] = sum_f Wq[k,64j+f]*srk[f];  d[j] = bq[j]::srk ----
    if (tid < 256) {
        int j = tid & 3, k = tid >> 2;
        const float* wt = g_WT + g * 16384 + j * 4096;   // WT[(j*64+f)*64 + k]
        float a = 0.f;
        #pragma unroll
        for (int f = 0; f < 64; f++)
            a += wt[f * 64 + k] * s_srk[f];
        s_c[j * 68 + k] = a;
    } else if (tid < 260) {
        int j = tid - 256;
        const float* bq = g ? eqb : nqb;
        float dd = 0.f;
        #pragma unroll
        for (int f = 0; f < 64; f++) dd += bq[j * 64 + f] * s_srk[f];
        s_d[j] = dd;
    }
    __syncthreads();

    // ---- phase 3: logits for all 3072 positions ----
    float lmax = -1e30f;
    #pragma unroll
    for (int i = 0; i < 3; i++) {
        int n = tid + i * 1024;
        int m = n >> 2, j = n & 3;
        const float4* row = (const float4*)(in + ((size_t)(h * RPH + m)) * 64);
        const float4* cj  = (const float4*)(s_c + j * 68);
        float a0 = 0.f, a1 = 0.f, a2 = 0.f, a3 = 0.f;
        #pragma unroll
        for (int k = 0; k < 16; k += 4) {
            float4 r0 = row[k + 0], c0 = cj[k + 0];
            float4 r1 = row[k + 1], c1 = cj[k + 1];
            float4 r2 = row[k + 2], c2 = cj[k + 2];
            float4 r3 = row[k + 3], c3 = cj[k + 3];
            a0 += r0.x * c0.x + r0.y * c0.y + r0.z * c0.z + r0.w * c0.w;
            a1 += r1.x * c1.x + r1.y * c1.y + r1.z * c1.z + r1.w * c1.w;
            a2 += r2.x * c2.x + r2.y * c2.y + r2.z * c2.z + r2.w * c2.w;
            a3 += r3.x * c3.x + r3.y * c3.y + r3.z * c3.z + r3.w * c3.w;
        }
        float x = (s_d[j] + ((a0 + a1) + (a2 + a3))) * 0.125f;
        s_x[n] = x;
        lmax = fmaxf(lmax, x);
    }

    // ---- phase 4: softmax over 3072 ----
    #pragma unroll
    for (int o = 16; o > 0; o >>= 1)
        lmax = fmaxf(lmax, __shfl_xor_sync(0xffffffffu, lmax, o));
    if ((tid & 31) == 0) s_red[tid >> 5] = lmax;
    __syncthreads();
    if (tid == 0) {
        float m2 = s_red[0];
        #pragma unroll
        for (int i = 1; i < 32; i++) m2 = fmaxf(m2, s_red[i]);
        s_v = m2;
    }
    __syncthreads();
    float mx = s_v;
    float e0 = __expf(s_x[tid]        - mx);
    float e1 = __expf(s_x[tid + 1024] - mx);
    float e2 = __expf(s_x[tid + 2048] - mx);
    float lsum = e0 + e1 + e2;
    #pragma unroll
    for (int o = 16; o > 0; o >>= 1)
        lsum += __shfl_xor_sync(0xffffffffu, lsum, o);
    __syncthreads();
    if ((tid & 31) == 0) s_red[tid >> 5] = lsum;
    __syncthreads();
    if (tid == 0) {
        float s = 0.f;
        #pragma unroll
        for (int i = 0; i < 32; i++) s += s_red[i];
        s_v = 1.f / s;
    }
    __syncthreads();
    float inv = s_v;
    float* att = g_att + (g * 4 + h) * 3072;
    att[tid]        = e0 * inv;
    att[tid + 1024] = e1 * inv;
    att[tid + 2048] = e2 * inv;
}

// ======= kernel D: message-passing scatter; blocks 0-35 also reset table =======
__global__ void __launch_bounds__(256) kD(
    const int* src, const int* dst, const int* lgs, const int* lgd, float* out)
{
    int tid = threadIdx.x;
    int bx = blockIdx.x;

    // restore tournament-table zero invariant (nothing reads g_tab this launch)
    if (bx < 36) {
        int e = bx * 256 + tid;
        if (e < EE) g_tab[src[e] * 3072 + dst[e]] = 0;
        else {
            int l = e - EE;
            g_tab[TABH + lgs[l] * 3072 + lgd[l]] = 0;
        }
    }

    int u = tid >> 6, f = tid & 63;
    if (bx < 768) {                                    // node messages (use edge att, g=1)
        int e = bx * 4 + u;
        if (!g_winN[e]) return;
        int s = src[e], d = dst[e];
        float acc = 0.f;
        #pragma unroll
        for (int h = 0; h < 4; h++)
            acc += __ldg(&g_att[(4 + h) * 3072 + e]) * g_NV[((size_t)(h * 3072 + d)) * 64 + f];
        atomicAdd(&out[s * 64 + f], 0.25f * acc);      // mean over heads
    } else {                                           // line-graph messages (use node att, g=0)
        int l = (bx - 768) * 4 + u;
        if (!g_winL[l]) return;
        int e1 = lgs[l], e2 = lgd[l];
        int c = dst[e1];
        float acc = 0.f;
        #pragma unroll
        for (int h = 0; h < 4; h++)
            acc += __ldg(&g_att[h * 3072 + c]) * g_EV[((size_t)(h * 3072 + e2)) * 64 + f];
        atomicAdd(&out[NN * 64 + e1 * 64 + f], 0.25f * acc);
    }
}

extern "C" void kernel_launch(void* const* d_in, const int* in_sizes, int n_in,
                              void* d_out, int out_size)
{
    const float* nin = (const float*)d_in[0];
    const float* ein = (const float*)d_in[1];
    const int* src = (const int*)d_in[2];
    const int* dst = (const int*)d_in[3];
    const int* lgs = (const int*)d_in[4];
    const int* lgd = (const int*)d_in[5];
    const float* nqW = (const float*)d_in[6];  const float* nqb = (const float*)d_in[7];
    const float* nkW = (const float*)d_in[8];  const float* nkb = (const float*)d_in[9];
    const float* nvW = (const float*)d_in[10]; const float* nvb = (const float*)d_in[11];
    const float* eqW = (const float*)d_in[12]; const float* eqb = (const float*)d_in[13];
    const float* ekW = (const float*)d_in[14]; const float* ekb = (const float*)d_in[15];
    const float* evW = (const float*)d_in[16]; const float* evb = (const float*)d_in[17];
    float* out = (float*)d_out;

    kA<<<908, 256>>>(nin, ein, nkW, nkb, ekW, ekb, nvW, nvb, evW, evb,
                     nqW, eqW, src, dst, lgs, lgd, out);
    kBC<<<17, 1024>>>(nin, ein, nqb, eqb, src, dst, lgs, lgd);
    kD<<<2304, 256>>>(src, dst, lgs, lgd, out);
}